// round 1
// baseline (speedup 1.0000x reference)
#include <cuda_runtime.h>
#include <cstdint>
#include <math.h>

// ============================================================================
// ARDiscriminator on GB300 — round 0 (exact fp32, f32x2-packed SIMT GEMMs)
//
// Key algorithmic cut: output only depends on feats[:, :, 511]; WaveNet
// receptive field is 256, so the encoder runs only on frames t in [256,512)
// (2048 frames) and the WaveNet on a 256-wide window with zero padding
// (provably exact for the needed dependency cone).
// ============================================================================

// ---------------- f32x2 helpers (2x fp32 FMA rate on sm_103a) -------------
__device__ __forceinline__ unsigned long long pack2(float x) {
    unsigned long long r;
    asm("mov.b64 %0, {%1, %1};" : "=l"(r) : "f"(x));
    return r;
}
__device__ __forceinline__ void fma2(unsigned long long& d,
                                     unsigned long long a,
                                     unsigned long long b) {
    asm("fma.rn.f32x2 %0, %1, %2, %0;" : "+l"(d) : "l"(a), "l"(b));
}
__device__ __forceinline__ float2 unpack2(unsigned long long v) {
    float2 r;
    asm("mov.b64 {%0, %1}, %2;" : "=f"(r.x), "=f"(r.y) : "l"(v));
    return r;
}

// ---------------- static scratch (no runtime allocation) ------------------
#define NFRAMES 2048   // 8 batches x 256 needed frames (t in [256,512))

__device__ __align__(128) float g_bufA[(size_t)NFRAMES * 128 * 128]; // 134 MB
__device__ __align__(128) float g_bufB[(size_t)NFRAMES * 128 * 64];  //  67 MB
__device__ __align__(128) float g_H  [NFRAMES * 256];                // [col=b*256+tt][co]
__device__ __align__(128) float g_Ht [256 * NFRAMES];                // [ci][col]
__device__ __align__(128) float g_pre[2 * NFRAMES * 256];            // main/gate preact
__device__ __align__(128) float g_Fz [2048];                         // feats[:, :, 511]
__device__ __align__(128) float g_wt123 [3 * 896 * 128];             // transposed weights
__device__ __align__(128) float g_wt4567[4 * 384 * 128];
__device__ __align__(128) float g_wt8   [128 * 256];
__device__ __align__(128) float g_wvt   [8 * 2 * 512 * 256];

// ---------------- weight transpose + Fz zero -------------------------------
// Transposed layout: wt[kidx][co], kidx = ci*KW + kw  (coalesced GEMM A loads)
__global__ void prep_weights(const float* __restrict__ w123,
                             const float* __restrict__ w4567,
                             const float* __restrict__ w8,
                             const float* __restrict__ wm,
                             const float* __restrict__ wg) {
    const int stride = gridDim.x * blockDim.x;
    const int t0 = blockIdx.x * blockDim.x + threadIdx.x;

    for (int e = t0; e < 3 * 896 * 128; e += stride) {
        int l = e / (896 * 128);
        int r = e % (896 * 128);
        int kidx = r >> 7, co = r & 127;
        int ci = kidx / 7, kw = kidx % 7;
        g_wt123[e] = w123[((l * 128 + co) * 128 + ci) * 7 + kw];
    }
    for (int e = t0; e < 4 * 384 * 128; e += stride) {
        int l = e / (384 * 128);
        int r = e % (384 * 128);
        int kidx = r >> 7, co = r & 127;
        int ci = kidx / 3, kw = kidx % 3;
        g_wt4567[e] = w4567[((l * 128 + co) * 128 + ci) * 3 + kw];
    }
    for (int e = t0; e < 128 * 256; e += stride) {
        int ci = e >> 8, co = e & 255;
        g_wt8[e] = w8[co * 128 + ci];
    }
    // wavenet: kidx = ci*2 + tap ; element [l][z][kidx][co]
    for (int e = t0; e < 8 * 2 * 512 * 256; e += stride) {
        int lz = e / (512 * 256);
        int r = e % (512 * 256);
        int l = lz >> 1, z = lz & 1;
        int kidx = r >> 8, co = r & 255;
        const float* w = z ? wg : wm;
        g_wvt[e] = w[(l * 256 + co) * 512 + kidx]; // (co-row stride 512, flat (ci,tap))
    }
    for (int e = t0; e < 2048; e += stride) g_Fz[e] = 0.f;
}

// ---------------- encoder conv0 (Cin=1, K=7, s=2, pad 3) -------------------
// one CTA per needed frame; frame f = b*256 + tt, global t = tt + 256
__global__ void conv0_kernel(const float* __restrict__ x,
                             const float* __restrict__ w0) {
    __shared__ float xin[256];
    __shared__ float w0s[896];
    const int f = blockIdx.x;
    const int b = f >> 8, tt = f & 255, t = tt + 256;
    const int tid = threadIdx.x;

    xin[tid] = x[(b * 256 + tid) * 512 + t];
    for (int i = tid; i < 896; i += 256) w0s[i] = w0[i];
    __syncthreads();

    const int co = tid >> 1;
    const int pb = (tid & 1) << 6;
    float* outp = &g_bufA[((size_t)f * 128 + co) * 128];
    #pragma unroll 4
    for (int u = 0; u < 64; u++) {
        int p = pb + u;
        float s = 0.f;
        #pragma unroll
        for (int k = 0; k < 7; k++) {
            int ip = 2 * p + k - 3;
            float xv = (ip >= 0 && ip < 256) ? xin[ip] : 0.f;
            s = fmaf(w0s[co * 7 + k], xv, s);
        }
        outp[p] = s > 0.f ? s : 0.2f * s;
    }
}

// ---------------- generic conv-as-GEMM (stride 2) --------------------------
// out[f][co][p] = act( sum_{ci,kw} wt[ci*KW+kw][co] * in[f][ci][2p+kw-PAD] )
// M = COUT (tile 128 via blockIdx.y), N = NFRAMES*LOUT, K = CIN*KW
template <int CIN, int COUT, int KW, int PAD, int LIN, int LOUT, int NT, bool RELU>
__global__ __launch_bounds__(256, 2)
void conv_gemm(const float* __restrict__ in,
               const float* __restrict__ wt,
               float* __restrict__ out) {
    constexpr int K   = CIN * KW;
    constexpr int KT  = 8;
    constexpr int TN  = NT / 16;   // 8 (NT=128) or 4 (NT=64)
    constexpr int TN2 = TN / 2;
    constexpr int PER = (KT * NT) / 256;

    __shared__ __align__(16) float As[KT * 128];
    __shared__ __align__(16) float Bs[KT * NT];

    const int tid = threadIdx.x;
    const int tm = tid >> 4, tn = tid & 15;
    const int col0 = blockIdx.x * NT;
    const int m0 = blockIdx.y * 128;

    unsigned long long acc[8][TN2];
    #pragma unroll
    for (int i = 0; i < 8; i++)
        #pragma unroll
        for (int j = 0; j < TN2; j++) acc[i][j] = 0ULL;

    for (int k0 = 0; k0 < K; k0 += KT) {
        // A tile: weights (coalesced float4)
        {
            int kk = tid >> 5;
            int m = (tid & 31) << 2;
            *reinterpret_cast<float4*>(&As[kk * 128 + m]) =
                *reinterpret_cast<const float4*>(&wt[(k0 + kk) * COUT + m0 + m]);
        }
        // B tile: on-the-fly im2col
        {
            int kk = tid >> 5;
            int cb = (tid & 31) * PER;
            int kidx = k0 + kk;
            int ci = kidx / KW;
            int kw = kidx % KW;
            #pragma unroll
            for (int j = 0; j < PER; j++) {
                int c = cb + j;
                int col = col0 + c;
                int f = col / LOUT;
                int p = col % LOUT;
                int ip = 2 * p + kw - PAD;
                float v = 0.f;
                if (ip >= 0 && ip < LIN) v = in[((size_t)f * CIN + ci) * LIN + ip];
                Bs[kk * NT + c] = v;
            }
        }
        __syncthreads();
        #pragma unroll
        for (int kk = 0; kk < KT; kk++) {
            float4 alo = *reinterpret_cast<const float4*>(&As[kk * 128 + tm * 8]);
            float4 ahi = *reinterpret_cast<const float4*>(&As[kk * 128 + tm * 8 + 4]);
            unsigned long long a2[8];
            a2[0] = pack2(alo.x); a2[1] = pack2(alo.y);
            a2[2] = pack2(alo.z); a2[3] = pack2(alo.w);
            a2[4] = pack2(ahi.x); a2[5] = pack2(ahi.y);
            a2[6] = pack2(ahi.z); a2[7] = pack2(ahi.w);
            unsigned long long b2[TN2];
            #pragma unroll
            for (int j = 0; j < TN2; j++)
                b2[j] = *reinterpret_cast<const unsigned long long*>(
                            &Bs[kk * NT + tn * TN + 2 * j]);
            #pragma unroll
            for (int i = 0; i < 8; i++)
                #pragma unroll
                for (int j = 0; j < TN2; j++) fma2(acc[i][j], a2[i], b2[j]);
        }
        __syncthreads();
    }

    // epilogue
    #pragma unroll
    for (int i = 0; i < 8; i++) {
        int co = m0 + tm * 8 + i;
        #pragma unroll
        for (int j = 0; j < TN2; j++) {
            float2 v = unpack2(acc[i][j]);
            int col = col0 + tn * TN + 2 * j;
            float x0 = v.x, x1 = v.y;
            if (RELU) {
                x0 = x0 > 0.f ? x0 : 0.2f * x0;
                x1 = x1 > 0.f ? x1 : 0.2f * x1;
            }
            int f0 = col / LOUT, p0 = col % LOUT;
            int f1 = (col + 1) / LOUT, p1 = (col + 1) % LOUT;
            out[((size_t)f0 * COUT + co) * LOUT + p0] = x0;
            out[((size_t)f1 * COUT + co) * LOUT + p1] = x1;
        }
    }
}

// ---------------- H transpose: Ht[ci][col] = H[col][ci] --------------------
__global__ void transposeH() {
    int idx = blockIdx.x * 256 + threadIdx.x; // 524288
    int ci = idx >> 11;
    int col = idx & 2047;
    g_Ht[idx] = g_H[col * 256 + ci];
}

// ---------------- WaveNet GEMM (main+gate), K = 512 = 256ci x 2taps --------
// pre[z][col][co] = sum_ci (W[z][co][ci][0]*H[tt-dil][ci] + W[z][co][ci][1]*H[tt][ci])
__global__ __launch_bounds__(256, 2)
void wn_gemm(int layer, int dil) {
    constexpr int K = 512, NT = 64, KT = 8, TN = 4, TN2 = 2, PER = 2;
    __shared__ __align__(16) float As[KT * 128];
    __shared__ __align__(16) float Bs[KT * NT];

    const int tid = threadIdx.x;
    const int tm = tid >> 4, tn = tid & 15;
    const int col0 = blockIdx.x * NT;
    const int m0 = blockIdx.y * 128;
    const int zsel = blockIdx.z;
    const float* wt = g_wvt + (size_t)(layer * 2 + zsel) * 512 * 256;

    unsigned long long acc[8][TN2];
    #pragma unroll
    for (int i = 0; i < 8; i++)
        #pragma unroll
        for (int j = 0; j < TN2; j++) acc[i][j] = 0ULL;

    for (int k0 = 0; k0 < K; k0 += KT) {
        {
            int kk = tid >> 5;
            int m = (tid & 31) << 2;
            *reinterpret_cast<float4*>(&As[kk * 128 + m]) =
                *reinterpret_cast<const float4*>(&wt[(k0 + kk) * 256 + m0 + m]);
        }
        {
            int kk = tid >> 5;
            int cb = (tid & 31) * PER;
            int kidx = k0 + kk;
            int ci = kidx >> 1;
            int tap = kidx & 1;
            const float* hrow = g_Ht + ci * 2048;
            #pragma unroll
            for (int j = 0; j < PER; j++) {
                int c = cb + j;
                int col = col0 + c;
                int tt = col & 255;
                float v = 0.f;
                if (tap) v = hrow[col];
                else if (tt >= dil) v = hrow[col - dil];
                Bs[kk * NT + c] = v;
            }
        }
        __syncthreads();
        #pragma unroll
        for (int kk = 0; kk < KT; kk++) {
            float4 alo = *reinterpret_cast<const float4*>(&As[kk * 128 + tm * 8]);
            float4 ahi = *reinterpret_cast<const float4*>(&As[kk * 128 + tm * 8 + 4]);
            unsigned long long a2[8];
            a2[0] = pack2(alo.x); a2[1] = pack2(alo.y);
            a2[2] = pack2(alo.z); a2[3] = pack2(alo.w);
            a2[4] = pack2(ahi.x); a2[5] = pack2(ahi.y);
            a2[6] = pack2(ahi.z); a2[7] = pack2(ahi.w);
            unsigned long long b2[TN2];
            #pragma unroll
            for (int j = 0; j < TN2; j++)
                b2[j] = *reinterpret_cast<const unsigned long long*>(
                            &Bs[kk * NT + tn * TN + 2 * j]);
            #pragma unroll
            for (int i = 0; i < 8; i++)
                #pragma unroll
                for (int j = 0; j < TN2; j++) fma2(acc[i][j], a2[i], b2[j]);
        }
        __syncthreads();
    }

    float* pre = g_pre + (size_t)zsel * NFRAMES * 256;
    #pragma unroll
    for (int i = 0; i < 8; i++) {
        int co = m0 + tm * 8 + i;
        #pragma unroll
        for (int j = 0; j < TN2; j++) {
            float2 v = unpack2(acc[i][j]);
            int col = col0 + tn * TN + 2 * j;
            pre[(size_t)col * 256 + co] = v.x;
            pre[(size_t)(col + 1) * 256 + co] = v.y;
        }
    }
}

// ---------------- WaveNet pointwise: z = tanh*sigmoid; H += z; Fz += z@tt=255
__global__ void wn_pointwise() {
    int idx = blockIdx.x * 256 + threadIdx.x; // 524288
    float pm = g_pre[idx];
    float pg = g_pre[NFRAMES * 256 + idx];
    float z = tanhf(pm) * (1.f / (1.f + expf(-pg)));
    g_H[idx] += z;
    int col = idx >> 8;
    if ((col & 255) == 255) {
        int b = col >> 8;
        g_Fz[b * 256 + (idx & 255)] += z;
    }
}

// ---------------- finalize: latent last frame + judge ----------------------
__global__ void finalize_kernel(const float* __restrict__ jw,
                                float* __restrict__ out, int out_size) {
    __shared__ float red[256];
    const int b = blockIdx.x;
    const int t = threadIdx.x;
    float v = g_Fz[b * 256 + t];
    out[b * 256 + t] = v;
    red[t] = v * jw[t];
    __syncthreads();
    #pragma unroll
    for (int s = 128; s > 0; s >>= 1) {
        if (t < s) red[t] += red[t + s];
        __syncthreads();
    }
    if (t == 0 && out_size >= 2048 + 8) out[2048 + b] = red[0];
}

// ---------------- launch ----------------------------------------------------
extern "C" void kernel_launch(void* const* d_in, const int* in_sizes, int n_in,
                              void* d_out, int out_size) {
    const float* x      = (const float*)d_in[0];
    const float* w0     = (const float*)d_in[1];
    const float* w123   = (const float*)d_in[2];
    const float* w4567  = (const float*)d_in[3];
    const float* w8     = (const float*)d_in[4];
    const float* wm     = (const float*)d_in[5];
    const float* wg     = (const float*)d_in[6];
    const float* jw     = (const float*)d_in[7];
    float* out = (float*)d_out;

    float *pA, *pB, *pH, *pW123, *pW4567, *pW8;
    cudaGetSymbolAddress((void**)&pA, g_bufA);
    cudaGetSymbolAddress((void**)&pB, g_bufB);
    cudaGetSymbolAddress((void**)&pH, g_H);
    cudaGetSymbolAddress((void**)&pW123, g_wt123);
    cudaGetSymbolAddress((void**)&pW4567, g_wt4567);
    cudaGetSymbolAddress((void**)&pW8, g_wt8);

    prep_weights<<<512, 256>>>(w123, w4567, w8, wm, wg);
    conv0_kernel<<<NFRAMES, 256>>>(x, w0);

    // encoder layers (CIN,COUT,KW,PAD,LIN,LOUT,NT,RELU); grid.x = NFRAMES*LOUT/NT
    conv_gemm<128,128,7,3,128,64,128,true><<<dim3(1024,1), 256>>>(pA, pW123,              pB);
    conv_gemm<128,128,7,3, 64,32,128,true><<<dim3( 512,1), 256>>>(pB, pW123 +   896*128,  pA);
    conv_gemm<128,128,7,3, 32,16,128,true><<<dim3( 256,1), 256>>>(pA, pW123 + 2*896*128,  pB);
    conv_gemm<128,128,3,1, 16, 8,128,true><<<dim3( 128,1), 256>>>(pB, pW4567,             pA);
    conv_gemm<128,128,3,1,  8, 4, 64,true><<<dim3( 128,1), 256>>>(pA, pW4567 +   384*128, pB);
    conv_gemm<128,128,3,1,  4, 2, 64,true><<<dim3(  64,1), 256>>>(pB, pW4567 + 2*384*128, pA);
    conv_gemm<128,128,3,1,  2, 1, 64,true><<<dim3(  32,1), 256>>>(pA, pW4567 + 3*384*128, pB);
    conv_gemm<128,256,1,0,  1, 1, 64,false><<<dim3( 32,2), 256>>>(pB, pW8,                pH);

    // WaveNet stack over the 256-frame window
    for (int l = 0; l < 8; l++) {
        transposeH<<<2048, 256>>>();
        wn_gemm<<<dim3(32, 2, 2), 256>>>(l, 1 << l);
        wn_pointwise<<<2048, 256>>>();
    }

    finalize_kernel<<<8, 256>>>(jw, out, out_size);
}

// round 3
// speedup vs baseline: 2.0901x; 2.0901x over previous
#include <cuda_runtime.h>
#include <cuda_bf16.h>
#include <cstdint>
#include <math.h>

// ============================================================================
// ARDiscriminator on GB300 — round 2: portable bf16 mma.sync (HMMA) GEMMs.
// tcgen05 is rejected by the harness's .target sm_103 PTX, so we use the
// sm_80-portable mma.sync path (still tensor cores).
//
// - Only frames t in [256,512) matter (WaveNet receptive field = 256).
// - bf16 hi/lo 3-term split keeps accuracy (~2^-17 per product).
// - latent = H_final - H_enc (residual telescoping).
// ============================================================================

#define NFRAMES 2048

__device__ __align__(128) float g_bufA[(size_t)NFRAMES * 128 * 128];
__device__ __align__(128) float g_bufB[(size_t)NFRAMES * 128 * 64];
__device__ __align__(128) float g_H   [NFRAMES * 256];      // [col][co]
__device__ __align__(128) float g_pre [2 * NFRAMES * 256];  // main/gate preact
__device__ __align__(128) float g_Henc[2048];

// ---------------- low-level helpers ----------------------------------------
__device__ __forceinline__ uint32_t smem_u32(const void* p) {
    uint32_t a;
    asm("{ .reg .u64 t; cvta.to.shared.u64 t, %1; cvt.u32.u64 %0, t; }"
        : "=r"(a) : "l"(p));
    return a;
}

__device__ __forceinline__ void ldsm_x4(uint32_t (&r)[4], uint32_t addr) {
    asm volatile("ldmatrix.sync.aligned.m8n8.x4.shared.b16 {%0,%1,%2,%3}, [%4];"
                 : "=r"(r[0]), "=r"(r[1]), "=r"(r[2]), "=r"(r[3]) : "r"(addr));
}
__device__ __forceinline__ void ldsm_x2(uint32_t (&r)[2], uint32_t addr) {
    asm volatile("ldmatrix.sync.aligned.m8n8.x2.shared.b16 {%0,%1}, [%2];"
                 : "=r"(r[0]), "=r"(r[1]) : "r"(addr));
}
__device__ __forceinline__ void mma_bf16(float (&c)[4], const uint32_t (&a)[4],
                                         const uint32_t (&b)[2]) {
    asm volatile(
        "mma.sync.aligned.m16n8k16.row.col.f32.bf16.bf16.f32 "
        "{%0,%1,%2,%3}, {%4,%5,%6,%7}, {%8,%9}, {%0,%1,%2,%3};"
        : "+f"(c[0]), "+f"(c[1]), "+f"(c[2]), "+f"(c[3])
        : "r"(a[0]), "r"(a[1]), "r"(a[2]), "r"(a[3]), "r"(b[0]), "r"(b[1]));
}

// fp32 -> bf16 hi/lo split, 8 values -> two uint4 (packed bf16x2)
__device__ __forceinline__ void split8(const float* v, uint4& hi, uint4& lo) {
    uint32_t h[8], l[8];
#pragma unroll
    for (int j = 0; j < 8; j++) {
        __nv_bfloat16 hb = __float2bfloat16(v[j]);
        float r = v[j] - __bfloat162float(hb);
        __nv_bfloat16 lb = __float2bfloat16(r);
        h[j] = (uint32_t)__bfloat16_as_ushort(hb);
        l[j] = (uint32_t)__bfloat16_as_ushort(lb);
    }
    hi = make_uint4(h[0] | (h[1] << 16), h[2] | (h[3] << 16),
                    h[4] | (h[5] << 16), h[6] | (h[7] << 16));
    lo = make_uint4(l[0] | (l[1] << 16), l[2] | (l[3] << 16),
                    l[4] | (l[5] << 16), l[6] | (l[7] << 16));
}

__device__ __forceinline__ int sw128(int off) { return off ^ ((off >> 3) & 0x70); }

__device__ __forceinline__ void sts16_sw(char* base, int off, uint4 v) {
    *reinterpret_cast<uint4*>(base + sw128(off)) = v;
}

// SMEM layout: A tiles 128 rows x 64 k (bf16, 128B rows), B tiles 64 x 64.
static constexpr int SM_A_HI = 0;
static constexpr int SM_A_LO = 16384;
static constexpr int SM_B_HI = 32768;
static constexpr int SM_B_LO = 40960;
static constexpr int SMEM_TOTAL = 49152;   // static 48KB exactly

// warp-tile compute over one 64-wide K slab (3-term split)
__device__ __forceinline__ void compute_slab(uint32_t sb, int lane, int wm, int wn_,
                                             float (&c)[2][4][4]) {
#pragma unroll
    for (int kc = 0; kc < 64; kc += 16) {
        uint32_t bh[4][2], bl[4][2];
#pragma unroll
        for (int ni = 0; ni < 4; ni++) {
            int off = (wn_ + ni * 8 + (lane & 7)) * 128 +
                      (kc + ((lane >> 3) & 1) * 8) * 2;
            int swo = sw128(off);
            ldsm_x2(bh[ni], sb + SM_B_HI + swo);
            ldsm_x2(bl[ni], sb + SM_B_LO + swo);
        }
#pragma unroll
        for (int mi = 0; mi < 2; mi++) {
            int off = (wm + mi * 16 + (lane & 7) + ((lane >> 3) & 1) * 8) * 128 +
                      (kc + (lane >> 4) * 8) * 2;
            int swo = sw128(off);
            uint32_t ah[4], al[4];
            ldsm_x4(ah, sb + SM_A_HI + swo);
            ldsm_x4(al, sb + SM_A_LO + swo);
#pragma unroll
            for (int ni = 0; ni < 4; ni++) {
                mma_bf16(c[mi][ni], ah, bh[ni]);
                mma_bf16(c[mi][ni], ah, bl[ni]);
                mma_bf16(c[mi][ni], al, bh[ni]);
            }
        }
    }
}

// ---------------- encoder conv0 (Cin=1, K=7, s=2, pad 3) -------------------
__global__ void conv0_kernel(const float* __restrict__ x,
                             const float* __restrict__ w0) {
    __shared__ float xin[256];
    __shared__ float w0s[896];
    const int f = blockIdx.x;
    const int b = f >> 8, t = (f & 255) + 256;
    const int tid = threadIdx.x;

    xin[tid] = x[(b * 256 + tid) * 512 + t];
    for (int i = tid; i < 896; i += 256) w0s[i] = w0[i];
    __syncthreads();

    const int co = tid >> 1;
    const int pb = (tid & 1) << 6;
    float* outp = &g_bufA[((size_t)f * 128 + co) * 128];
#pragma unroll 4
    for (int u = 0; u < 64; u++) {
        int p = pb + u;
        float s = 0.f;
#pragma unroll
        for (int k = 0; k < 7; k++) {
            int ip = 2 * p + k - 3;
            float xv = (ip >= 0 && ip < 256) ? xin[ip] : 0.f;
            s = fmaf(w0s[co * 7 + k], xv, s);
        }
        outp[p] = s > 0.f ? s : 0.2f * s;
    }
}

// ---------------- conv-as-GEMM via mma.sync ---------------------------------
// D[co][col] = sum_{ci,kw} W[co][ci][kw] * in[f][ci][2p+kw-PAD]
// CTA tile: M=128 (blockIdx.y), N=64 (blockIdx.x); 8 warps of 32x32.
template <int CIN, int COUT, int KW, int PAD, int LIN, int LOUT, bool RELU, bool COLMAJOR>
__global__ __launch_bounds__(256, 2)
void conv_mma(const float* __restrict__ in, const float* __restrict__ w,
              float* __restrict__ out) {
    constexpr int K = CIN * KW;
    constexpr int NST = K / 64;
    __shared__ __align__(1024) char smem[SMEM_TOTAL];
    const uint32_t sb = smem_u32(smem);

    const int tid = threadIdx.x;
    const int lane = tid & 31;
    const int warp = tid >> 5;
    const int wm = (warp >> 1) * 32;
    const int wn_ = (warp & 1) * 32;
    const int col0 = blockIdx.x * 64;
    const int m0 = blockIdx.y * 128;

    float c[2][4][4];
#pragma unroll
    for (int i = 0; i < 2; i++)
#pragma unroll
        for (int j = 0; j < 4; j++)
#pragma unroll
            for (int k = 0; k < 4; k++) c[i][j][k] = 0.f;

    for (int s = 0; s < NST; s++) {
        const int k0 = s * 64;
        __syncthreads();
        // A tile: weights, native [co][ci*KW+kw] rows
#pragma unroll
        for (int g = 0; g < 4; g++) {
            int gi = tid + g * 256;          // 0..1023
            int row = gi >> 3, kb = gi & 7;
            const float* src = w + (size_t)(m0 + row) * K + k0 + kb * 8;
            float4 v0 = *reinterpret_cast<const float4*>(src);
            float4 v1 = *reinterpret_cast<const float4*>(src + 4);
            float v[8] = {v0.x, v0.y, v0.z, v0.w, v1.x, v1.y, v1.z, v1.w};
            uint4 hi, lo;
            split8(v, hi, lo);
            int off = row * 128 + kb * 16;
            sts16_sw(smem + SM_A_HI, off, hi);
            sts16_sw(smem + SM_A_LO, off, lo);
        }
        // B tile: on-the-fly im2col
#pragma unroll
        for (int g = 0; g < 2; g++) {
            int gi = tid + g * 256;          // 0..511
            int row = gi >> 3, kb = gi & 7;
            int col = col0 + row;
            int f = col / LOUT, p = col % LOUT;
            float v[8];
#pragma unroll
            for (int j = 0; j < 8; j++) {
                int k = k0 + kb * 8 + j;
                int ci = k / KW, kw = k % KW;
                int ip = 2 * p + kw - PAD;
                v[j] = (ip >= 0 && ip < LIN)
                           ? in[((size_t)f * CIN + ci) * LIN + ip] : 0.f;
            }
            uint4 hi, lo;
            split8(v, hi, lo);
            int off = row * 128 + kb * 16;
            sts16_sw(smem + SM_B_HI, off, hi);
            sts16_sw(smem + SM_B_LO, off, lo);
        }
        __syncthreads();
        compute_slab(sb, lane, wm, wn_, c);
    }

    // epilogue
#pragma unroll
    for (int mi = 0; mi < 2; mi++) {
#pragma unroll
        for (int ni = 0; ni < 4; ni++) {
            int r0 = m0 + wm + mi * 16 + (lane >> 2);
            int colb = col0 + wn_ + ni * 8 + (lane & 3) * 2;
#pragma unroll
            for (int e = 0; e < 4; e++) {
                int row = r0 + (e >> 1) * 8;
                int col = colb + (e & 1);
                float xv = c[mi][ni][e];
                if (RELU) xv = xv > 0.f ? xv : 0.2f * xv;
                if (COLMAJOR) {
                    out[(size_t)col * 256 + row] = xv;
                } else {
                    int f = col / LOUT, p = col % LOUT;
                    out[((size_t)f * COUT + row) * LOUT + p] = xv;
                }
            }
        }
    }
}

// ---------------- WaveNet GEMM (main+gate) ----------------------------------
// pre[z][col][co] = sum_{ci,tap} W[z][co][ci][tap] * Hsel ; K = 512
__global__ __launch_bounds__(256, 2)
void wn_mma(const float* __restrict__ wmain, const float* __restrict__ wgate,
            int layer, int dil) {
    __shared__ __align__(1024) char smem[SMEM_TOTAL];
    const uint32_t sb = smem_u32(smem);

    const int tid = threadIdx.x;
    const int lane = tid & 31;
    const int warp = tid >> 5;
    const int wm = (warp >> 1) * 32;
    const int wn_ = (warp & 1) * 32;
    const int col0 = blockIdx.x * 64;
    const int z = blockIdx.y >> 1;
    const int mh = blockIdx.y & 1;
    const float* w = (z ? wgate : wmain) + ((size_t)layer * 256 + mh * 128) * 512;

    float c[2][4][4];
#pragma unroll
    for (int i = 0; i < 2; i++)
#pragma unroll
        for (int j = 0; j < 4; j++)
#pragma unroll
            for (int k = 0; k < 4; k++) c[i][j][k] = 0.f;

    for (int s = 0; s < 8; s++) {
        const int k0 = s * 64;
        __syncthreads();
#pragma unroll
        for (int g = 0; g < 4; g++) {     // A tile
            int gi = tid + g * 256;
            int row = gi >> 3, kb = gi & 7;
            const float* src = w + (size_t)row * 512 + k0 + kb * 8;
            float4 v0 = *reinterpret_cast<const float4*>(src);
            float4 v1 = *reinterpret_cast<const float4*>(src + 4);
            float v[8] = {v0.x, v0.y, v0.z, v0.w, v1.x, v1.y, v1.z, v1.w};
            uint4 hi, lo;
            split8(v, hi, lo);
            int off = row * 128 + kb * 16;
            sts16_sw(smem + SM_A_HI, off, hi);
            sts16_sw(smem + SM_A_LO, off, lo);
        }
#pragma unroll
        for (int g = 0; g < 2; g++) {     // B tile from H (dilated taps)
            int gi = tid + g * 256;
            int row = gi >> 3, kb = gi & 7;
            int col = col0 + row;
            int tt = col & 255;
            float v[8];
#pragma unroll
            for (int j = 0; j < 8; j++) {
                int k = k0 + kb * 8 + j;
                int ci = k >> 1, tap = k & 1;
                if (tap) v[j] = g_H[(size_t)col * 256 + ci];
                else     v[j] = (tt >= dil) ? g_H[(size_t)(col - dil) * 256 + ci] : 0.f;
            }
            uint4 hi, lo;
            split8(v, hi, lo);
            int off = row * 128 + kb * 16;
            sts16_sw(smem + SM_B_HI, off, hi);
            sts16_sw(smem + SM_B_LO, off, lo);
        }
        __syncthreads();
        compute_slab(sb, lane, wm, wn_, c);
    }

    float* pre = g_pre + (size_t)z * NFRAMES * 256;
#pragma unroll
    for (int mi = 0; mi < 2; mi++) {
#pragma unroll
        for (int ni = 0; ni < 4; ni++) {
            int r0 = mh * 128 + wm + mi * 16 + (lane >> 2);
            int colb = col0 + wn_ + ni * 8 + (lane & 3) * 2;
#pragma unroll
            for (int e = 0; e < 4; e++) {
                int row = r0 + (e >> 1) * 8;
                int col = colb + (e & 1);
                pre[(size_t)col * 256 + row] = c[mi][ni][e];
            }
        }
    }
}

// ---------------- pointwise / stash / finalize ------------------------------
__global__ void wn_pointwise() {
    int idx = blockIdx.x * 256 + threadIdx.x;       // 524288
    float pm = g_pre[idx];
    float pg = g_pre[NFRAMES * 256 + idx];
    float zv = tanhf(pm) * (1.f / (1.f + expf(-pg)));
    g_H[idx] += zv;
}

__global__ void stash_henc() {
    int i = blockIdx.x * 256 + threadIdx.x;         // 2048
    int b = i >> 8, co = i & 255;
    g_Henc[i] = g_H[((size_t)b * 256 + 255) * 256 + co];
}

__global__ void finalize_kernel(const float* __restrict__ jw,
                                float* __restrict__ out, int out_size) {
    __shared__ float red[256];
    const int b = blockIdx.x;
    const int t = threadIdx.x;
    float v = g_H[((size_t)b * 256 + 255) * 256 + t] - g_Henc[b * 256 + t];
    out[b * 256 + t] = v;
    red[t] = v * jw[t];
    __syncthreads();
#pragma unroll
    for (int s = 128; s > 0; s >>= 1) {
        if (t < s) red[t] += red[t + s];
        __syncthreads();
    }
    if (t == 0 && out_size >= 2048 + 8) out[2048 + b] = red[0];
}

// ---------------- launch -----------------------------------------------------
extern "C" void kernel_launch(void* const* d_in, const int* in_sizes, int n_in,
                              void* d_out, int out_size) {
    const float* x     = (const float*)d_in[0];
    const float* w0    = (const float*)d_in[1];
    const float* w123  = (const float*)d_in[2];
    const float* w4567 = (const float*)d_in[3];
    const float* w8    = (const float*)d_in[4];
    const float* wm    = (const float*)d_in[5];
    const float* wg    = (const float*)d_in[6];
    const float* jw    = (const float*)d_in[7];
    float* out = (float*)d_out;

    float *pA, *pB, *pH;
    cudaGetSymbolAddress((void**)&pA, g_bufA);
    cudaGetSymbolAddress((void**)&pB, g_bufB);
    cudaGetSymbolAddress((void**)&pH, g_H);

    conv0_kernel<<<NFRAMES, 256>>>(x, w0);

    // (CIN,COUT,KW,PAD,LIN,LOUT,RELU,COLMAJOR); grid = (NFRAMES*LOUT/64, COUT/128)
    conv_mma<128,128,7,3,128,64,true ,false><<<dim3(2048,1), 256>>>(pA, w123,              pB);
    conv_mma<128,128,7,3, 64,32,true ,false><<<dim3(1024,1), 256>>>(pB, w123 + 1*128*896,  pA);
    conv_mma<128,128,7,3, 32,16,true ,false><<<dim3( 512,1), 256>>>(pA, w123 + 2*128*896,  pB);
    conv_mma<128,128,3,1, 16, 8,true ,false><<<dim3( 256,1), 256>>>(pB, w4567,             pA);
    conv_mma<128,128,3,1,  8, 4,true ,false><<<dim3( 128,1), 256>>>(pA, w4567 + 1*128*384, pB);
    conv_mma<128,128,3,1,  4, 2,true ,false><<<dim3(  64,1), 256>>>(pB, w4567 + 2*128*384, pA);
    conv_mma<128,128,3,1,  2, 1,true ,false><<<dim3(  32,1), 256>>>(pA, w4567 + 3*128*384, pB);
    conv_mma<128,256,1,0,  1, 1,false,true ><<<dim3(  32,2), 256>>>(pB, w8,                pH);

    stash_henc<<<8, 256>>>();

    for (int l = 0; l < 8; l++) {
        wn_mma<<<dim3(32, 4), 256>>>(wm, wg, l, 1 << l);
        wn_pointwise<<<2048, 256>>>();
    }

    finalize_kernel<<<8, 256>>>(jw, out, out_size);
}

// round 5
// speedup vs baseline: 4.0484x; 1.9370x over previous
#include <cuda_runtime.h>
#include <cuda_bf16.h>
#include <cstdint>
#include <math.h>

// ============================================================================
// ARDiscriminator on GB300 — round 4: (= round 3 design, compile fix)
// mma.sync bf16x3 GEMMs with pre-split hi/lo operand planes +
// cp.async double-buffered fills.
//
// - Only frames t in [256,512) matter (WaveNet receptive field = 256).
// - All operands pre-split to bf16 hi/lo planes, channel-last, k-reordered
//   (k = kw*128 + ci), so every K-slab row is 128B contiguous -> cp.async.
// - 3-term split MMA (hi*hi + hi*lo + lo*hi), error ~2^-17 per product.
// - latent = H_final - H_enc (residual telescoping).
// ============================================================================

#define NFRAMES 2048

template <int N> struct ILog2 { static constexpr int v = 1 + ILog2<N / 2>::v; };
template <> struct ILog2<1> { static constexpr int v = 0; };

// ---------------- static scratch -------------------------------------------
__device__ __align__(128) __nv_bfloat16 g_pAhi[(size_t)NFRAMES * 128 * 128];
__device__ __align__(128) __nv_bfloat16 g_pAlo[(size_t)NFRAMES * 128 * 128];
__device__ __align__(128) __nv_bfloat16 g_pBhi[(size_t)NFRAMES * 64 * 128];
__device__ __align__(128) __nv_bfloat16 g_pBlo[(size_t)NFRAMES * 64 * 128];
__device__ __align__(128) float         g_H   [NFRAMES * 256];
__device__ __align__(128) __nv_bfloat16 g_Hhi [NFRAMES * 256];
__device__ __align__(128) __nv_bfloat16 g_Hlo [NFRAMES * 256];
__device__ __align__(128) float         g_pre [2 * NFRAMES * 256];
__device__ __align__(128) float         g_Henc[2048];
// weight planes (k-reordered)
__device__ __align__(128) __nv_bfloat16 g_w123hi [3 * 128 * 896];
__device__ __align__(128) __nv_bfloat16 g_w123lo [3 * 128 * 896];
__device__ __align__(128) __nv_bfloat16 g_w4567hi[4 * 128 * 384];
__device__ __align__(128) __nv_bfloat16 g_w4567lo[4 * 128 * 384];
__device__ __align__(128) __nv_bfloat16 g_w8hi   [256 * 128];
__device__ __align__(128) __nv_bfloat16 g_w8lo   [256 * 128];
__device__ __align__(128) __nv_bfloat16 g_wnhi   [8 * 2 * 256 * 512];
__device__ __align__(128) __nv_bfloat16 g_wnlo   [8 * 2 * 256 * 512];

// ---------------- low-level helpers ----------------------------------------
__device__ __forceinline__ uint32_t smem_u32(const void* p) {
    uint32_t a;
    asm("{ .reg .u64 t; cvta.to.shared.u64 t, %1; cvt.u32.u64 %0, t; }"
        : "=r"(a) : "l"(p));
    return a;
}
__device__ __forceinline__ void cp16(uint32_t dst, const void* src, int sz) {
    asm volatile("cp.async.cg.shared.global [%0], [%1], 16, %2;"
                 :: "r"(dst), "l"(src), "r"(sz));
}
#define CP_COMMIT() asm volatile("cp.async.commit_group;")
#define CP_WAIT1()  asm volatile("cp.async.wait_group 1;")
#define CP_WAIT0()  asm volatile("cp.async.wait_group 0;")

__device__ __forceinline__ void ldsm_x4(uint32_t (&r)[4], uint32_t addr) {
    asm volatile("ldmatrix.sync.aligned.m8n8.x4.shared.b16 {%0,%1,%2,%3}, [%4];"
                 : "=r"(r[0]), "=r"(r[1]), "=r"(r[2]), "=r"(r[3]) : "r"(addr));
}
__device__ __forceinline__ void ldsm_x2(uint32_t (&r)[2], uint32_t addr) {
    asm volatile("ldmatrix.sync.aligned.m8n8.x2.shared.b16 {%0,%1}, [%2];"
                 : "=r"(r[0]), "=r"(r[1]) : "r"(addr));
}
__device__ __forceinline__ void mma_bf16(float (&c)[4], const uint32_t (&a)[4],
                                         const uint32_t (&b)[2]) {
    asm volatile(
        "mma.sync.aligned.m16n8k16.row.col.f32.bf16.bf16.f32 "
        "{%0,%1,%2,%3}, {%4,%5,%6,%7}, {%8,%9}, {%0,%1,%2,%3};"
        : "+f"(c[0]), "+f"(c[1]), "+f"(c[2]), "+f"(c[3])
        : "r"(a[0]), "r"(a[1]), "r"(a[2]), "r"(a[3]), "r"(b[0]), "r"(b[1]));
}

__device__ __forceinline__ int sw128(int off) { return off ^ ((off >> 3) & 0x70); }

__device__ __forceinline__ void split1(float v, __nv_bfloat16& h, __nv_bfloat16& l) {
    h = __float2bfloat16(v);
    l = __float2bfloat16(v - __bfloat162float(h));
}

// SMEM tile offsets within one pipeline buffer
static constexpr int SM_A_HI = 0;
static constexpr int SM_A_LO = 16384;
static constexpr int SM_B_HI = 32768;
static constexpr int SM_B_LO = 40960;
static constexpr int BUFSZ   = 49152;
static constexpr int SMEM_PIPE = 2 * BUFSZ;  // 96KB dynamic

// warp-tile compute over one 64-wide K slab (3-term split)
__device__ __forceinline__ void compute_slab(uint32_t base, int lane, int wm, int wn_,
                                             float (&c)[2][4][4]) {
#pragma unroll
    for (int kc = 0; kc < 64; kc += 16) {
        uint32_t bh[4][2], bl[4][2];
#pragma unroll
        for (int ni = 0; ni < 4; ni++) {
            int off = (wn_ + ni * 8 + (lane & 7)) * 128 +
                      (kc + ((lane >> 3) & 1) * 8) * 2;
            int swo = sw128(off);
            ldsm_x2(bh[ni], base + SM_B_HI + swo);
            ldsm_x2(bl[ni], base + SM_B_LO + swo);
        }
#pragma unroll
        for (int mi = 0; mi < 2; mi++) {
            int off = (wm + mi * 16 + (lane & 7) + ((lane >> 3) & 1) * 8) * 128 +
                      (kc + (lane >> 4) * 8) * 2;
            int swo = sw128(off);
            uint32_t ah[4], al[4];
            ldsm_x4(ah, base + SM_A_HI + swo);
            ldsm_x4(al, base + SM_A_LO + swo);
#pragma unroll
            for (int ni = 0; ni < 4; ni++) {
                mma_bf16(c[mi][ni], ah, bh[ni]);
                mma_bf16(c[mi][ni], ah, bl[ni]);
                mma_bf16(c[mi][ni], al, bh[ni]);
            }
        }
    }
}

// ---------------- weight prep: split + k-reorder -----------------------------
__global__ void prep_weights(const float* __restrict__ w123,
                             const float* __restrict__ w4567,
                             const float* __restrict__ w8,
                             const float* __restrict__ wm,
                             const float* __restrict__ wg) {
    const int stride = gridDim.x * blockDim.x;
    const int t0 = blockIdx.x * blockDim.x + threadIdx.x;
    for (int e = t0; e < 3 * 128 * 896; e += stride) {
        int l = e / (128 * 896), r = e % (128 * 896);
        int co = r / 896, k = r % 896;
        int kw = k >> 7, ci = k & 127;
        split1(w123[((l * 128 + co) * 128 + ci) * 7 + kw], g_w123hi[e], g_w123lo[e]);
    }
    for (int e = t0; e < 4 * 128 * 384; e += stride) {
        int l = e / (128 * 384), r = e % (128 * 384);
        int co = r / 384, k = r % 384;
        int kw = k >> 7, ci = k & 127;
        split1(w4567[((l * 128 + co) * 128 + ci) * 3 + kw], g_w4567hi[e], g_w4567lo[e]);
    }
    for (int e = t0; e < 256 * 128; e += stride) {
        int co = e >> 7, ci = e & 127;
        split1(w8[co * 128 + ci], g_w8hi[e], g_w8lo[e]);
    }
    for (int e = t0; e < 8 * 2 * 256 * 512; e += stride) {
        int lz = e / (256 * 512), r = e % (256 * 512);
        int co = r / 512, k = r % 512;
        int tap = k >> 8, ci = k & 255;
        int l = lz >> 1, z = lz & 1;
        const float* w = z ? wg : wm;
        split1(w[((l * 256 + co) * 256 + ci) * 2 + tap], g_wnhi[e], g_wnlo[e]);
    }
}

// ---------------- encoder conv0 (Cin=1, K=7, s=2, pad 3) --------------------
// writes channel-last hi/lo planes: g_pA*[((f*128)+p)*128 + co]
__global__ void conv0_kernel(const float* __restrict__ x,
                             const float* __restrict__ w0) {
    __shared__ float xin[256];
    __shared__ float w0s[896];
    const int f = blockIdx.x;
    const int b = f >> 8, t = (f & 255) + 256;
    const int tid = threadIdx.x;

    xin[tid] = x[(b * 256 + tid) * 512 + t];
    for (int i = tid; i < 896; i += 256) w0s[i] = w0[i];
    __syncthreads();

    const int co = tid & 127;
    const int ph = tid >> 7;
#pragma unroll 4
    for (int u = 0; u < 64; u++) {
        int p = ph * 64 + u;
        float s = 0.f;
#pragma unroll
        for (int k = 0; k < 7; k++) {
            int ip = 2 * p + k - 3;
            float xv = (ip >= 0 && ip < 256) ? xin[ip] : 0.f;
            s = fmaf(w0s[co * 7 + k], xv, s);
        }
        s = s > 0.f ? s : 0.2f * s;
        size_t o = ((size_t)f * 128 + p) * 128 + co;
        split1(s, g_pAhi[o], g_pAlo[o]);
    }
}

// ---------------- conv-as-GEMM: cp.async pipeline + mma.sync ----------------
// CTA tile M=128 x N=64; K consumed in 64-wide slabs (kw-major k order).
template <int KW, int PAD, int LIN, int LOUT, bool RELU, bool LAST>
__global__ __launch_bounds__(256, 2)
void conv_mma2(const __nv_bfloat16* __restrict__ in_hi,
               const __nv_bfloat16* __restrict__ in_lo,
               const __nv_bfloat16* __restrict__ w_hi,
               const __nv_bfloat16* __restrict__ w_lo,
               __nv_bfloat16* __restrict__ out_hi,
               __nv_bfloat16* __restrict__ out_lo) {
    constexpr int K = KW * 128;
    constexpr int NST = K / 64;
    constexpr int LOG = ILog2<LOUT>::v;
    extern __shared__ __align__(1024) char smem[];
    const uint32_t sb = smem_u32(smem);

    const int tid = threadIdx.x;
    const int lane = tid & 31;
    const int warp = tid >> 5;
    const int wm = (warp >> 1) * 32;
    const int wn_ = (warp & 1) * 32;
    const int col0 = blockIdx.x * 64;
    const int m0 = blockIdx.y * 128;

    float c[2][4][4];
#pragma unroll
    for (int i = 0; i < 2; i++)
#pragma unroll
        for (int j = 0; j < 4; j++)
#pragma unroll
            for (int k = 0; k < 4; k++) c[i][j][k] = 0.f;

    auto issue = [&](int s) {
        const uint32_t bo = sb + (s & 1) * BUFSZ;
        const int kw = s >> 1;
        const int ci0 = (s & 1) * 64;
        // A tile: 128 rows x 128B, contiguous rows of weight plane
#pragma unroll
        for (int g = 0; g < 4; g++) {
            int gi = tid + g * 256;
            int row = gi >> 3, j = gi & 7;
            uint32_t off = row * 128 + ((j ^ (row & 7)) << 4);
            size_t so = (size_t)(m0 + row) * K + s * 64 + j * 8;
            cp16(bo + SM_A_HI + off, w_hi + so, 16);
            cp16(bo + SM_A_LO + off, w_lo + so, 16);
        }
        // B tile: 64 rows x 128B, contiguous ci runs of activation plane
#pragma unroll
        for (int g = 0; g < 2; g++) {
            int gi = tid + g * 256;
            int row = gi >> 3, j = gi & 7;
            int col = col0 + row;
            int f = col >> LOG;
            int p = col & (LOUT - 1);
            int ip = 2 * p + kw - PAD;
            bool v = ((unsigned)ip < (unsigned)LIN);
            size_t so = ((size_t)f * LIN + (v ? ip : 0)) * 128 + ci0 + j * 8;
            int sz = v ? 16 : 0;
            uint32_t off = row * 128 + ((j ^ (row & 7)) << 4);
            cp16(bo + SM_B_HI + off, in_hi + so, sz);
            cp16(bo + SM_B_LO + off, in_lo + so, sz);
        }
    };

    issue(0);
    CP_COMMIT();
    for (int s = 0; s < NST; s++) {
        if (s + 1 < NST) { issue(s + 1); CP_COMMIT(); CP_WAIT1(); }
        else             { CP_WAIT0(); }
        __syncthreads();
        compute_slab(sb + (s & 1) * BUFSZ, lane, wm, wn_, c);
        __syncthreads();
    }

    // epilogue: write hi/lo planes (channel-last) or H (+planes) for LAST
#pragma unroll
    for (int mi = 0; mi < 2; mi++) {
#pragma unroll
        for (int ni = 0; ni < 4; ni++) {
            int r0 = wm + mi * 16 + (lane >> 2);
            int colb = col0 + wn_ + ni * 8 + (lane & 3) * 2;
#pragma unroll
            for (int e = 0; e < 4; e++) {
                int row = r0 + (e >> 1) * 8;
                int col = colb + (e & 1);
                float xv = c[mi][ni][e];
                if (RELU) xv = xv > 0.f ? xv : 0.2f * xv;
                if (LAST) {
                    size_t o = (size_t)col * 256 + m0 + row;
                    g_H[o] = xv;
                    split1(xv, g_Hhi[o], g_Hlo[o]);
                } else {
                    size_t o = (size_t)col * 128 + row;   // (f*LOUT+p)*128 + co
                    split1(xv, out_hi[o], out_lo[o]);
                }
            }
        }
    }
}

// ---------------- WaveNet GEMM (main+gate), K = 512 (tap-major) -------------
__global__ __launch_bounds__(256, 2)
void wn_mma2(int layer, int dil) {
    extern __shared__ __align__(1024) char smem[];
    const uint32_t sb = smem_u32(smem);

    const int tid = threadIdx.x;
    const int lane = tid & 31;
    const int warp = tid >> 5;
    const int wm = (warp >> 1) * 32;
    const int wn_ = (warp & 1) * 32;
    const int col0 = blockIdx.x * 64;
    const int z = blockIdx.y >> 1;
    const int mh = blockIdx.y & 1;
    const __nv_bfloat16* w_hi = g_wnhi + ((size_t)(layer * 2 + z) * 256 + mh * 128) * 512;
    const __nv_bfloat16* w_lo = g_wnlo + ((size_t)(layer * 2 + z) * 256 + mh * 128) * 512;

    float c[2][4][4];
#pragma unroll
    for (int i = 0; i < 2; i++)
#pragma unroll
        for (int j = 0; j < 4; j++)
#pragma unroll
            for (int k = 0; k < 4; k++) c[i][j][k] = 0.f;

    auto issue = [&](int s) {
        const uint32_t bo = sb + (s & 1) * BUFSZ;
        const int tap = s >> 2;
        const int ci0 = (s & 3) * 64;
#pragma unroll
        for (int g = 0; g < 4; g++) {
            int gi = tid + g * 256;
            int row = gi >> 3, j = gi & 7;
            uint32_t off = row * 128 + ((j ^ (row & 7)) << 4);
            size_t so = (size_t)row * 512 + s * 64 + j * 8;
            cp16(bo + SM_A_HI + off, w_hi + so, 16);
            cp16(bo + SM_A_LO + off, w_lo + so, 16);
        }
#pragma unroll
        for (int g = 0; g < 2; g++) {
            int gi = tid + g * 256;
            int row = gi >> 3, j = gi & 7;
            int col = col0 + row;
            int tt = col & 255;
            bool v = tap ? true : (tt >= dil);
            int scol = tap ? col : (v ? col - dil : col);
            size_t so = (size_t)scol * 256 + ci0 + j * 8;
            int sz = v ? 16 : 0;
            uint32_t off = row * 128 + ((j ^ (row & 7)) << 4);
            cp16(bo + SM_B_HI + off, g_Hhi + so, sz);
            cp16(bo + SM_B_LO + off, g_Hlo + so, sz);
        }
    };

    issue(0);
    CP_COMMIT();
    for (int s = 0; s < 8; s++) {
        if (s + 1 < 8) { issue(s + 1); CP_COMMIT(); CP_WAIT1(); }
        else           { CP_WAIT0(); }
        __syncthreads();
        compute_slab(sb + (s & 1) * BUFSZ, lane, wm, wn_, c);
        __syncthreads();
    }

    float* pre = g_pre + (size_t)z * NFRAMES * 256;
#pragma unroll
    for (int mi = 0; mi < 2; mi++) {
#pragma unroll
        for (int ni = 0; ni < 4; ni++) {
            int r0 = mh * 128 + wm + mi * 16 + (lane >> 2);
            int colb = col0 + wn_ + ni * 8 + (lane & 3) * 2;
#pragma unroll
            for (int e = 0; e < 4; e++) {
                int row = r0 + (e >> 1) * 8;
                int col = colb + (e & 1);
                pre[(size_t)col * 256 + row] = c[mi][ni][e];
            }
        }
    }
}

// ---------------- pointwise / stash / finalize ------------------------------
__global__ void wn_pointwise() {
    int idx = blockIdx.x * 256 + threadIdx.x;       // 524288
    float pm = g_pre[idx];
    float pg = g_pre[NFRAMES * 256 + idx];
    float zv = tanhf(pm) * (1.f / (1.f + expf(-pg)));
    float h = g_H[idx] + zv;
    g_H[idx] = h;
    split1(h, g_Hhi[idx], g_Hlo[idx]);
}

__global__ void stash_henc() {
    int i = blockIdx.x * 256 + threadIdx.x;         // 2048
    int b = i >> 8, co = i & 255;
    g_Henc[i] = g_H[((size_t)b * 256 + 255) * 256 + co];
}

__global__ void finalize_kernel(const float* __restrict__ jw,
                                float* __restrict__ out, int out_size) {
    __shared__ float red[256];
    const int b = blockIdx.x;
    const int t = threadIdx.x;
    float v = g_H[((size_t)b * 256 + 255) * 256 + t] - g_Henc[b * 256 + t];
    out[b * 256 + t] = v;
    red[t] = v * jw[t];
    __syncthreads();
#pragma unroll
    for (int s = 128; s > 0; s >>= 1) {
        if (t < s) red[t] += red[t + s];
        __syncthreads();
    }
    if (t == 0 && out_size >= 2048 + 8) out[2048 + b] = red[0];
}

// ---------------- launch -----------------------------------------------------
extern "C" void kernel_launch(void* const* d_in, const int* in_sizes, int n_in,
                              void* d_out, int out_size) {
    const float* x     = (const float*)d_in[0];
    const float* w0    = (const float*)d_in[1];
    const float* w123  = (const float*)d_in[2];
    const float* w4567 = (const float*)d_in[3];
    const float* w8    = (const float*)d_in[4];
    const float* wm    = (const float*)d_in[5];
    const float* wg    = (const float*)d_in[6];
    const float* jw    = (const float*)d_in[7];
    float* out = (float*)d_out;

    __nv_bfloat16 *pAhi, *pAlo, *pBhi, *pBlo;
    __nv_bfloat16 *w123hi, *w123lo, *w4567hi, *w4567lo, *w8hi, *w8lo;
    cudaGetSymbolAddress((void**)&pAhi, g_pAhi);
    cudaGetSymbolAddress((void**)&pAlo, g_pAlo);
    cudaGetSymbolAddress((void**)&pBhi, g_pBhi);
    cudaGetSymbolAddress((void**)&pBlo, g_pBlo);
    cudaGetSymbolAddress((void**)&w123hi, g_w123hi);
    cudaGetSymbolAddress((void**)&w123lo, g_w123lo);
    cudaGetSymbolAddress((void**)&w4567hi, g_w4567hi);
    cudaGetSymbolAddress((void**)&w4567lo, g_w4567lo);
    cudaGetSymbolAddress((void**)&w8hi, g_w8hi);
    cudaGetSymbolAddress((void**)&w8lo, g_w8lo);

    cudaFuncSetAttribute(conv_mma2<7,3,128,64,true ,false>, cudaFuncAttributeMaxDynamicSharedMemorySize, SMEM_PIPE);
    cudaFuncSetAttribute(conv_mma2<7,3, 64,32,true ,false>, cudaFuncAttributeMaxDynamicSharedMemorySize, SMEM_PIPE);
    cudaFuncSetAttribute(conv_mma2<7,3, 32,16,true ,false>, cudaFuncAttributeMaxDynamicSharedMemorySize, SMEM_PIPE);
    cudaFuncSetAttribute(conv_mma2<3,1, 16, 8,true ,false>, cudaFuncAttributeMaxDynamicSharedMemorySize, SMEM_PIPE);
    cudaFuncSetAttribute(conv_mma2<3,1,  8, 4,true ,false>, cudaFuncAttributeMaxDynamicSharedMemorySize, SMEM_PIPE);
    cudaFuncSetAttribute(conv_mma2<3,1,  4, 2,true ,false>, cudaFuncAttributeMaxDynamicSharedMemorySize, SMEM_PIPE);
    cudaFuncSetAttribute(conv_mma2<3,1,  2, 1,true ,false>, cudaFuncAttributeMaxDynamicSharedMemorySize, SMEM_PIPE);
    cudaFuncSetAttribute(conv_mma2<1,0,  1, 1,false,true >, cudaFuncAttributeMaxDynamicSharedMemorySize, SMEM_PIPE);
    cudaFuncSetAttribute(wn_mma2, cudaFuncAttributeMaxDynamicSharedMemorySize, SMEM_PIPE);

    prep_weights<<<512, 256>>>(w123, w4567, w8, wm, wg);
    conv0_kernel<<<NFRAMES, 256>>>(x, w0);

    // (KW,PAD,LIN,LOUT,RELU,LAST); grid = (NFRAMES*LOUT/64, COUT/128)
    conv_mma2<7,3,128,64,true ,false><<<dim3(2048,1), 256, SMEM_PIPE>>>(pAhi, pAlo, w123hi,               w123lo,               pBhi, pBlo);
    conv_mma2<7,3, 64,32,true ,false><<<dim3(1024,1), 256, SMEM_PIPE>>>(pBhi, pBlo, w123hi + 1*128*896,   w123lo + 1*128*896,   pAhi, pAlo);
    conv_mma2<7,3, 32,16,true ,false><<<dim3( 512,1), 256, SMEM_PIPE>>>(pAhi, pAlo, w123hi + 2*128*896,   w123lo + 2*128*896,   pBhi, pBlo);
    conv_mma2<3,1, 16, 8,true ,false><<<dim3( 256,1), 256, SMEM_PIPE>>>(pBhi, pBlo, w4567hi,              w4567lo,              pAhi, pAlo);
    conv_mma2<3,1,  8, 4,true ,false><<<dim3( 128,1), 256, SMEM_PIPE>>>(pAhi, pAlo, w4567hi + 1*128*384,  w4567lo + 1*128*384,  pBhi, pBlo);
    conv_mma2<3,1,  4, 2,true ,false><<<dim3(  64,1), 256, SMEM_PIPE>>>(pBhi, pBlo, w4567hi + 2*128*384,  w4567lo + 2*128*384,  pAhi, pAlo);
    conv_mma2<3,1,  2, 1,true ,false><<<dim3(  32,1), 256, SMEM_PIPE>>>(pAhi, pAlo, w4567hi + 3*128*384,  w4567lo + 3*128*384,  pBhi, pBlo);
    conv_mma2<1,0,  1, 1,false,true ><<<dim3(  32,2), 256, SMEM_PIPE>>>(pBhi, pBlo, w8hi,                 w8lo,                 pAhi, pAlo);

    stash_henc<<<8, 256>>>();

    for (int l = 0; l < 8; l++) {
        wn_mma2<<<dim3(32, 4), 256, SMEM_PIPE>>>(l, 1 << l);
        wn_pointwise<<<2048, 256>>>();
    }

    finalize_kernel<<<8, 256>>>(jw, out, out_size);
}